// round 1
// baseline (speedup 1.0000x reference)
#include <cuda_runtime.h>
#include <cuda_bf16.h>
#include <math.h>

// ---------------- problem constants ----------------
#define B_SZ   2
#define SEQ_L  2048
#define DMODEL 1024
#define DINNER 2048
#define DSTATE 16
#define DTRANK 64
#define MROWS  (B_SZ * SEQ_L)          // 4096

// ---------------- scratch (device globals; no allocations allowed) -------
__device__ float g_xz   [(size_t)MROWS * 2 * DINNER];   // 4096 x 4096
__device__ float g_xconv[(size_t)MROWS * DINNER];       // 4096 x 2048
__device__ float g_dt   [(size_t)MROWS * DINNER];       // 4096 x 2048
__device__ float g_ys   [(size_t)MROWS * DINNER];       // 4096 x 2048
__device__ float g_pout [(size_t)MROWS * 128];          // 4096 x 128 (xdbl|B|C|pad)
__device__ float g_wpack[(size_t)128 * DINNER];         // packed proj weights

// ---------------- helpers ----------------
__device__ __forceinline__ float siluf(float v) {
    return v / (1.f + __expf(-v));
}
__device__ __forceinline__ float softplusf(float v) {
    return (v > 20.f) ? v : log1pf(expf(v));
}

// ---------------- generic fp32 SGEMM: C = A(MxK) * W(NxK)^T ----------------
// EPI: 0 = none, 1 = softplus(v + bias[n])
template<int BM, int BN, int TM, int TN, int EPI>
__global__ __launch_bounds__(256)
void sgemm_kernel(const float* __restrict__ A, const float* __restrict__ W,
                  const float* __restrict__ bias, float* __restrict__ C,
                  int M, int N, int K, int lda, int ldb, int ldc)
{
    constexpr int BK = 8;
    __shared__ float As[BK][BM];
    __shared__ float Ws[BK][BN];

    const int tid = threadIdx.x;
    const int bm  = blockIdx.y * BM;
    const int bn  = blockIdx.x * BN;

    constexpr int TCOLS = BN / TN;          // threads along N
    const int trow = (tid / TCOLS) * TM;
    const int tcol = (tid % TCOLS) * TN;

    float acc[TM][TN];
#pragma unroll
    for (int i = 0; i < TM; i++)
#pragma unroll
        for (int j = 0; j < TN; j++) acc[i][j] = 0.f;

    for (int k0 = 0; k0 < K; k0 += BK) {
        if (tid < BM * 2) {
            int r = tid >> 1, seg = (tid & 1) * 4;
            float4 v = *(const float4*)(A + (size_t)(bm + r) * lda + k0 + seg);
            As[seg + 0][r] = v.x; As[seg + 1][r] = v.y;
            As[seg + 2][r] = v.z; As[seg + 3][r] = v.w;
        }
        if (tid < BN * 2) {
            int r = tid >> 1, seg = (tid & 1) * 4;
            float4 v = *(const float4*)(W + (size_t)(bn + r) * ldb + k0 + seg);
            Ws[seg + 0][r] = v.x; Ws[seg + 1][r] = v.y;
            Ws[seg + 2][r] = v.z; Ws[seg + 3][r] = v.w;
        }
        __syncthreads();
#pragma unroll
        for (int kk = 0; kk < BK; kk++) {
            float a[TM], b[TN];
#pragma unroll
            for (int i = 0; i < TM; i++) a[i] = As[kk][trow + i];
#pragma unroll
            for (int j = 0; j < TN; j++) b[j] = Ws[kk][tcol + j];
#pragma unroll
            for (int i = 0; i < TM; i++)
#pragma unroll
                for (int j = 0; j < TN; j++)
                    acc[i][j] = fmaf(a[i], b[j], acc[i][j]);
        }
        __syncthreads();
    }

#pragma unroll
    for (int i = 0; i < TM; i++) {
#pragma unroll
        for (int j = 0; j < TN; j++) {
            int n = bn + tcol + j;
            float v = acc[i][j];
            if (EPI == 1) v = softplusf(v + bias[n]);
            C[(size_t)(bm + trow + i) * ldc + n] = v;
        }
    }
}

// ---------------- causal depthwise conv (k=4) + SiLU ----------------
__global__ void conv_silu_kernel(const float* __restrict__ xz,
                                 const float* __restrict__ cw,
                                 const float* __restrict__ cb,
                                 float* __restrict__ xc)
{
    int idx = blockIdx.x * blockDim.x + threadIdx.x;   // over MROWS*DINNER
    if (idx >= MROWS * DINNER) return;
    int d = idx & (DINNER - 1);
    int m = idx >> 11;              // DINNER = 2048 = 2^11
    int l = m & (SEQ_L - 1);

    float acc = cb[d];
#pragma unroll
    for (int j = 0; j < 4; j++) {
        int li = l - 3 + j;
        if (li >= 0)
            acc = fmaf(cw[d * 4 + j], xz[(size_t)(m - 3 + j) * (2 * DINNER) + d], acc);
    }
    xc[idx] = siluf(acc);
}

// ---------------- pack x_proj / B_proj / C_proj into 128 rows ----------------
__global__ void pack_w_kernel(const float* __restrict__ xp,
                              const float* __restrict__ bp,
                              const float* __restrict__ cp,
                              float* __restrict__ wp)
{
    int idx = blockIdx.x * blockDim.x + threadIdx.x;   // 128 * 2048
    if (idx >= 128 * DINNER) return;
    int r = idx >> 11, c = idx & (DINNER - 1);
    float v = 0.f;
    if (r < 64)       v = xp[r * DINNER + c];
    else if (r < 80)  v = bp[(r - 64) * DINNER + c];
    else if (r < 96)  v = cp[(r - 80) * DINNER + c];
    wp[idx] = v;
}

// ---------------- selective scan (sequential in L) ----------------
// thread = (b, d, s); block = 16 d-channels x 16 states; grid = B*DINNER/16
__global__ __launch_bounds__(256)
void scan_kernel(const float* __restrict__ xc, const float* __restrict__ dt,
                 const float* __restrict__ pout, const float* __restrict__ xz,
                 const float* __restrict__ A_log, const float* __restrict__ Dp,
                 float* __restrict__ ys)
{
    const int b    = blockIdx.x >> 7;       // 128 d-blocks per batch
    const int dblk = blockIdx.x & 127;
    const int s    = threadIdx.x & 15;
    const int dl   = threadIdx.x >> 4;
    const int d    = dblk * 16 + dl;

    const float Av = -__expf(A_log[d * DSTATE + s]);
    const float Dv = Dp[d];
    float h = 0.f;

    const float* xcp = xc   + (size_t)b * SEQ_L * DINNER + d;
    const float* dtp = dt   + (size_t)b * SEQ_L * DINNER + d;
    const float* Bp  = pout + (size_t)b * SEQ_L * 128 + 64 + s;
    const float* Cp  = Bp + 16;
    const float* zp  = xz   + (size_t)b * SEQ_L * (2 * DINNER) + DINNER + d;
    float*       yp  = ys   + (size_t)b * SEQ_L * DINNER + d;

    for (int l = 0; l < SEQ_L; l++) {
        float xv  = xcp[(size_t)l * DINNER];
        float dtv = dtp[(size_t)l * DINNER];
        float Bv  = Bp[(size_t)l * 128];
        float Cv  = Cp[(size_t)l * 128];

        h = fmaf(h, fmaf(dtv, Av, 1.f), dtv * Bv * xv);

        float p = h * Cv;
        p += __shfl_xor_sync(0xffffffffu, p, 1);
        p += __shfl_xor_sync(0xffffffffu, p, 2);
        p += __shfl_xor_sync(0xffffffffu, p, 4);
        p += __shfl_xor_sync(0xffffffffu, p, 8);

        if (s == 0) {
            float zv = zp[(size_t)l * (2 * DINNER)];
            float y  = fmaf(Dv, xv, p);
            yp[(size_t)l * DINNER] = y * siluf(zv);
        }
    }
}

// ---------------- launch ----------------
extern "C" void kernel_launch(void* const* d_in, const int* in_sizes, int n_in,
                              void* d_out, int out_size)
{
    const float* x         = (const float*)d_in[0];
    const float* in_proj_w = (const float*)d_in[1];
    const float* conv_w    = (const float*)d_in[2];
    const float* conv_b    = (const float*)d_in[3];
    const float* A_log     = (const float*)d_in[4];
    const float* Dp        = (const float*)d_in[5];
    const float* dt_proj_w = (const float*)d_in[6];
    const float* dt_proj_b = (const float*)d_in[7];
    const float* x_proj_w  = (const float*)d_in[8];
    const float* B_proj_w  = (const float*)d_in[9];
    const float* C_proj_w  = (const float*)d_in[10];
    const float* out_proj_w= (const float*)d_in[11];
    float* out = (float*)d_out;

    float *xz, *xc, *dt, *ys, *pout, *wpack;
    cudaGetSymbolAddress((void**)&xz,    g_xz);
    cudaGetSymbolAddress((void**)&xc,    g_xconv);
    cudaGetSymbolAddress((void**)&dt,    g_dt);
    cudaGetSymbolAddress((void**)&ys,    g_ys);
    cudaGetSymbolAddress((void**)&pout,  g_pout);
    cudaGetSymbolAddress((void**)&wpack, g_wpack);

    // 1. xz = x @ in_proj_w^T : (4096,1024)x(4096,1024)^T -> (4096,4096)
    sgemm_kernel<128,128,8,8,0><<<dim3(2*DINNER/128, MROWS/128), 256>>>(
        x, in_proj_w, nullptr, xz, MROWS, 2*DINNER, DMODEL, DMODEL, DMODEL, 2*DINNER);

    // 2. causal depthwise conv + silu
    conv_silu_kernel<<<(MROWS * DINNER + 255) / 256, 256>>>(xz, conv_w, conv_b, xc);

    // 3. pack projection weights (x|B|C, zero-padded to 128 rows)
    pack_w_kernel<<<(128 * DINNER + 255) / 256, 256>>>(x_proj_w, B_proj_w, C_proj_w, wpack);

    // 4. pout = xc @ wpack^T : (4096,2048)x(128,2048)^T -> (4096,128)
    sgemm_kernel<32,128,2,8,0><<<dim3(1, MROWS/32), 256>>>(
        xc, wpack, nullptr, pout, MROWS, 128, DINNER, DINNER, DINNER, 128);

    // 5. dt = softplus(xdbl @ dt_proj_w^T + b) : (4096,64)x(2048,64)^T
    sgemm_kernel<128,128,8,8,1><<<dim3(DINNER/128, MROWS/128), 256>>>(
        pout, dt_proj_w, dt_proj_b, dt, MROWS, DINNER, DTRANK, 128, DTRANK, DINNER);

    // 6. selective scan + D*x + silu(z) gating
    scan_kernel<<<B_SZ * (DINNER / 16), 256>>>(xc, dt, pout, xz, A_log, Dp, ys);

    // 7. out = ys @ out_proj_w^T : (4096,2048)x(1024,2048)^T -> (4096,1024)
    sgemm_kernel<128,128,8,8,0><<<dim3(DMODEL/128, MROWS/128), 256>>>(
        ys, out_proj_w, nullptr, out, MROWS, DMODEL, DINNER, DINNER, DINNER, DMODEL);
}

// round 15
// speedup vs baseline: 1.3761x; 1.3761x over previous
#include <cuda_runtime.h>
#include <cuda_bf16.h>
#include <math.h>
#include <cstdint>

// ---------------- problem constants ----------------
#define B_SZ   2
#define SEQ_L  2048
#define DMODEL 1024
#define DINNER 2048
#define DSTATE 16
#define DTRANK 64
#define MROWS  (B_SZ * SEQ_L)          // 4096

// ---------------- scratch ----------------
__device__ float g_xz   [(size_t)MROWS * 2 * DINNER];
__device__ float g_xconv[(size_t)MROWS * DINNER];
__device__ float g_dt   [(size_t)MROWS * DINNER];
__device__ float g_ys   [(size_t)MROWS * DINNER];
__device__ float g_pout [(size_t)MROWS * 128];
__device__ float g_wpack[(size_t)128 * DINNER];

// ---------------- helpers ----------------
__device__ __forceinline__ uint32_t smem_u32(const void* p) {
    uint32_t a;
    asm("{ .reg .u64 t; cvta.to.shared.u64 t, %1; cvt.u32.u64 %0, t; }" : "=r"(a) : "l"(p));
    return a;
}
__device__ __forceinline__ float siluf(float v)    { return v / (1.f + __expf(-v)); }
__device__ __forceinline__ float softplusf(float v){ return (v > 20.f) ? v : log1pf(expf(v)); }

__device__ __forceinline__ uint32_t pack2(__nv_bfloat16 a, __nv_bfloat16 b) {
    uint16_t ua = *reinterpret_cast<uint16_t*>(&a);
    uint16_t ub = *reinterpret_cast<uint16_t*>(&b);
    return ((uint32_t)ub << 16) | ua;
}

__device__ __forceinline__ void ldsm4(uint32_t* r, uint32_t addr) {
    asm volatile("ldmatrix.sync.aligned.m8n8.x4.shared.b16 {%0,%1,%2,%3}, [%4];"
        : "=r"(r[0]), "=r"(r[1]), "=r"(r[2]), "=r"(r[3]) : "r"(addr));
}

#define MMA16816(c, a, b0, b1) \
    asm volatile("mma.sync.aligned.m16n8k16.row.col.f32.bf16.bf16.f32 " \
        "{%0,%1,%2,%3}, {%4,%5,%6,%7}, {%8,%9}, {%0,%1,%2,%3};" \
        : "+f"((c)[0]), "+f"((c)[1]), "+f"((c)[2]), "+f"((c)[3]) \
        : "r"((a)[0]), "r"((a)[1]), "r"((a)[2]), "r"((a)[3]), "r"(b0), "r"(b1))

// SW128-equivalent swizzle for 128B rows: SWZ(r*128 + c) = r*128 + (c ^ ((r&7)<<4))

// ---------------- mma.sync GEMM: C = A(MxK) * W(NxK)^T ----------------
// hi/lo bf16 split precision (Ah*Bh + Ah*Bl + Al*Bh), fp32 accumulators.
// 128x128 CTA tile, 8 warps (2x4), warp tile 64x32, K-tiles of 64.
// SMEM: aH[16K] aL[16K] bH[16K] bL[16K] = 64KB dynamic, 2 CTA/SM.
// EPI: 0 = none, 1 = softplus(v + bias[n])
template<int EPI>
__global__ __launch_bounds__(256, 2)
void mma_gemm(const float* __restrict__ A, const float* __restrict__ W,
              const float* __restrict__ bias, float* __restrict__ C,
              int M, int N, int K, int lda, int ldb, int ldc)
{
    extern __shared__ char smem[];
    const uint32_t sb  = smem_u32(smem);
    const uint32_t sAH = sb, sAL = sb + 16384, sBH = sb + 32768, sBL = sb + 49152;

    const int tid  = threadIdx.x;
    const int wid  = tid >> 5;
    const int lane = tid & 31;
    const int bm = blockIdx.y * 128;
    const int bn = blockIdx.x * 128;
    const int wm = (wid >> 2) * 64;      // warp M offset: 0 / 64
    const int wn = (wid & 3) * 32;       // warp N offset: 0/32/64/96

    float acc[4][4][4];
#pragma unroll
    for (int i = 0; i < 4; i++)
#pragma unroll
        for (int j = 0; j < 4; j++)
#pragma unroll
            for (int k = 0; k < 4; k++) acc[i][j][k] = 0.f;

    // ldmatrix row-base byte offsets
    uint32_t aro[4], bro[2];
#pragma unroll
    for (int mt = 0; mt < 4; mt++) aro[mt] = (uint32_t)((wm + mt * 16 + (lane & 15)) * 128);
#pragma unroll
    for (int n2 = 0; n2 < 2; n2++) bro[n2] = (uint32_t)((wn + n2 * 16 + (lane & 15)) * 128);
    const uint32_t cxor  = (uint32_t)((lane & 7) << 4);
    const uint32_t chalf = (uint32_t)((lane >> 4) * 16);

    const int T = K >> 6;
    for (int t = 0; t < T; t++) {
        const float* Ab = A + (size_t)bm * lda + t * 64;
        const float* Wb = W + (size_t)bn * ldb + t * 64;

        // ---- load fp32, split to hi/lo bf16, store swizzled ----
#pragma unroll
        for (int j = 0; j < 8; j++) {
            int i  = tid + j * 256;              // 0..2047
            int r  = i >> 4;                     // row 0..127
            int c4 = (i & 15) << 2;              // col 0..60 step 4 (floats)
            uint32_t off = (uint32_t)(r * 128) + (uint32_t)((c4 * 2) ^ ((r & 7) << 4));

            float4 v = *(const float4*)(Ab + (size_t)r * lda + c4);
            __nv_bfloat16 h0 = __float2bfloat16_rn(v.x), h1 = __float2bfloat16_rn(v.y);
            __nv_bfloat16 h2 = __float2bfloat16_rn(v.z), h3 = __float2bfloat16_rn(v.w);
            *(uint2*)(smem + off) = make_uint2(pack2(h0, h1), pack2(h2, h3));
            __nv_bfloat16 l0 = __float2bfloat16_rn(v.x - __bfloat162float(h0));
            __nv_bfloat16 l1 = __float2bfloat16_rn(v.y - __bfloat162float(h1));
            __nv_bfloat16 l2 = __float2bfloat16_rn(v.z - __bfloat162float(h2));
            __nv_bfloat16 l3 = __float2bfloat16_rn(v.w - __bfloat162float(h3));
            *(uint2*)(smem + 16384 + off) = make_uint2(pack2(l0, l1), pack2(l2, l3));

            float4 w = *(const float4*)(Wb + (size_t)r * ldb + c4);
            h0 = __float2bfloat16_rn(w.x); h1 = __float2bfloat16_rn(w.y);
            h2 = __float2bfloat16_rn(w.z); h3 = __float2bfloat16_rn(w.w);
            *(uint2*)(smem + 32768 + off) = make_uint2(pack2(h0, h1), pack2(h2, h3));
            l0 = __float2bfloat16_rn(w.x - __bfloat162float(h0));
            l1 = __float2bfloat16_rn(w.y - __bfloat162float(h1));
            l2 = __float2bfloat16_rn(w.z - __bfloat162float(h2));
            l3 = __float2bfloat16_rn(w.w - __bfloat162float(h3));
            *(uint2*)(smem + 49152 + off) = make_uint2(pack2(l0, l1), pack2(l2, l3));
        }
        __syncthreads();

        // ---- 4 k16 steps ----
#pragma unroll
        for (int ks = 0; ks < 4; ks++) {
            const uint32_t cb = ((uint32_t)(ks * 32) + chalf) ^ cxor;
            uint32_t af[4][4], bh[2][4], bl[2][4];
#pragma unroll
            for (int mt = 0; mt < 4; mt++) ldsm4(af[mt], sAH + aro[mt] + cb);
#pragma unroll
            for (int n2 = 0; n2 < 2; n2++) ldsm4(bh[n2], sBH + bro[n2] + cb);
#pragma unroll
            for (int n2 = 0; n2 < 2; n2++) ldsm4(bl[n2], sBL + bro[n2] + cb);

            // Ah*Bh and Ah*Bl
#pragma unroll
            for (int mt = 0; mt < 4; mt++)
#pragma unroll
                for (int nt = 0; nt < 4; nt++) {
                    int n2 = nt >> 1, sel = nt & 1;
                    MMA16816(acc[mt][nt], af[mt], bh[n2][sel], bh[n2][sel + 2]);
                    MMA16816(acc[mt][nt], af[mt], bl[n2][sel], bl[n2][sel + 2]);
                }
            // Al*Bh (reuse af regs for lo)
#pragma unroll
            for (int mt = 0; mt < 4; mt++) ldsm4(af[mt], sAL + aro[mt] + cb);
#pragma unroll
            for (int mt = 0; mt < 4; mt++)
#pragma unroll
                for (int nt = 0; nt < 4; nt++) {
                    int n2 = nt >> 1, sel = nt & 1;
                    MMA16816(acc[mt][nt], af[mt], bh[n2][sel], bh[n2][sel + 2]);
                }
        }
        __syncthreads();
    }

    // ---- epilogue ----
    const int gid = lane >> 2;
    const int tig = (lane & 3) * 2;
#pragma unroll
    for (int mt = 0; mt < 4; mt++) {
#pragma unroll
        for (int nt = 0; nt < 4; nt++) {
            int col = bn + wn + nt * 8 + tig;
            int r0  = bm + wm + mt * 16 + gid;
            float v0 = acc[mt][nt][0], v1 = acc[mt][nt][1];
            float v2 = acc[mt][nt][2], v3 = acc[mt][nt][3];
            if (EPI == 1) {
                float b0 = bias[col], b1 = bias[col + 1];
                v0 = softplusf(v0 + b0); v1 = softplusf(v1 + b1);
                v2 = softplusf(v2 + b0); v3 = softplusf(v3 + b1);
            }
            *(float2*)(C + (size_t)r0 * ldc + col)       = make_float2(v0, v1);
            *(float2*)(C + (size_t)(r0 + 8) * ldc + col) = make_float2(v2, v3);
        }
    }
}

#define SMEM_GEMM_BYTES 65536

// ---------------- causal depthwise conv (k=4) + SiLU ----------------
__global__ void conv_silu_kernel(const float* __restrict__ xz,
                                 const float* __restrict__ cw,
                                 const float* __restrict__ cb,
                                 float* __restrict__ xc)
{
    int idx = blockIdx.x * blockDim.x + threadIdx.x;
    if (idx >= MROWS * DINNER) return;
    int d = idx & (DINNER - 1);
    int m = idx >> 11;
    int l = m & (SEQ_L - 1);

    float acc = cb[d];
#pragma unroll
    for (int j = 0; j < 4; j++) {
        int li = l - 3 + j;
        if (li >= 0)
            acc = fmaf(cw[d * 4 + j], xz[(size_t)(m - 3 + j) * (2 * DINNER) + d], acc);
    }
    xc[idx] = siluf(acc);
}

// ---------------- pack x_proj / B_proj / C_proj into 128 rows ----------------
__global__ void pack_w_kernel(const float* __restrict__ xp,
                              const float* __restrict__ bp,
                              const float* __restrict__ cp,
                              float* __restrict__ wp)
{
    int idx = blockIdx.x * blockDim.x + threadIdx.x;
    if (idx >= 128 * DINNER) return;
    int r = idx >> 11, c = idx & (DINNER - 1);
    float v = 0.f;
    if (r < 64)       v = xp[r * DINNER + c];
    else if (r < 80)  v = bp[(r - 64) * DINNER + c];
    else if (r < 96)  v = cp[(r - 80) * DINNER + c];
    wp[idx] = v;
}

// ---------------- selective scan ----------------
__global__ __launch_bounds__(256)
void scan_kernel(const float* __restrict__ xc, const float* __restrict__ dt,
                 const float* __restrict__ pout, const float* __restrict__ xz,
                 const float* __restrict__ A_log, const float* __restrict__ Dp,
                 float* __restrict__ ys)
{
    const int b    = blockIdx.x >> 7;
    const int dblk = blockIdx.x & 127;
    const int s    = threadIdx.x & 15;
    const int dl   = threadIdx.x >> 4;
    const int d    = dblk * 16 + dl;

    const float Av = -__expf(A_log[d * DSTATE + s]);
    const float Dv = Dp[d];
    float h = 0.f;

    const float* xcp = xc   + (size_t)b * SEQ_L * DINNER + d;
    const float* dtp = dt   + (size_t)b * SEQ_L * DINNER + d;
    const float* Bp  = pout + (size_t)b * SEQ_L * 128 + 64 + s;
    const float* Cp  = Bp + 16;
    const float* zp  = xz   + (size_t)b * SEQ_L * (2 * DINNER) + DINNER + d;
    float*       yp  = ys   + (size_t)b * SEQ_L * DINNER + d;

    for (int l = 0; l < SEQ_L; l++) {
        float xv  = xcp[(size_t)l * DINNER];
        float dtv = dtp[(size_t)l * DINNER];
        float Bv  = Bp[(size_t)l * 128];
        float Cv  = Cp[(size_t)l * 128];

        h = fmaf(h, fmaf(dtv, Av, 1.f), dtv * Bv * xv);

        float p = h * Cv;
        p += __shfl_xor_sync(0xffffffffu, p, 1);
        p += __shfl_xor_sync(0xffffffffu, p, 2);
        p += __shfl_xor_sync(0xffffffffu, p, 4);
        p += __shfl_xor_sync(0xffffffffu, p, 8);

        if (s == 0) {
            float zv = zp[(size_t)l * (2 * DINNER)];
            float y  = fmaf(Dv, xv, p);
            yp[(size_t)l * DINNER] = y * siluf(zv);
        }
    }
}

// ---------------- launch ----------------
extern "C" void kernel_launch(void* const* d_in, const int* in_sizes, int n_in,
                              void* d_out, int out_size)
{
    const float* x         = (const float*)d_in[0];
    const float* in_proj_w = (const float*)d_in[1];
    const float* conv_w    = (const float*)d_in[2];
    const float* conv_b    = (const float*)d_in[3];
    const float* A_log     = (const float*)d_in[4];
    const float* Dp        = (const float*)d_in[5];
    const float* dt_proj_w = (const float*)d_in[6];
    const float* dt_proj_b = (const float*)d_in[7];
    const float* x_proj_w  = (const float*)d_in[8];
    const float* B_proj_w  = (const float*)d_in[9];
    const float* C_proj_w  = (const float*)d_in[10];
    const float* out_proj_w= (const float*)d_in[11];
    float* out = (float*)d_out;

    float *xz, *xc, *dt, *ys, *pout, *wpack;
    cudaGetSymbolAddress((void**)&xz,    g_xz);
    cudaGetSymbolAddress((void**)&xc,    g_xconv);
    cudaGetSymbolAddress((void**)&dt,    g_dt);
    cudaGetSymbolAddress((void**)&ys,    g_ys);
    cudaGetSymbolAddress((void**)&pout,  g_pout);
    cudaGetSymbolAddress((void**)&wpack, g_wpack);

    cudaFuncSetAttribute(mma_gemm<0>, cudaFuncAttributeMaxDynamicSharedMemorySize, SMEM_GEMM_BYTES);
    cudaFuncSetAttribute(mma_gemm<1>, cudaFuncAttributeMaxDynamicSharedMemorySize, SMEM_GEMM_BYTES);

    // 1. xz = x @ in_proj_w^T : (4096,1024) x (4096,1024)^T
    mma_gemm<0><<<dim3(2 * DINNER / 128, MROWS / 128), 256, SMEM_GEMM_BYTES>>>(
        x, in_proj_w, nullptr, xz, MROWS, 2 * DINNER, DMODEL, DMODEL, DMODEL, 2 * DINNER);

    // 2. causal depthwise conv + silu
    conv_silu_kernel<<<(MROWS * DINNER + 255) / 256, 256>>>(xz, conv_w, conv_b, xc);

    // 3. pack x|B|C projection weights
    pack_w_kernel<<<(128 * DINNER + 255) / 256, 256>>>(x_proj_w, B_proj_w, C_proj_w, wpack);

    // 4. pout = xc @ wpack^T : (4096,2048) x (128,2048)^T
    mma_gemm<0><<<dim3(1, MROWS / 128), 256, SMEM_GEMM_BYTES>>>(
        xc, wpack, nullptr, pout, MROWS, 128, DINNER, DINNER, DINNER, 128);

    // 5. dt = softplus(xdbl @ dt_proj_w^T + b) : (4096,64) x (2048,64)^T
    mma_gemm<1><<<dim3(DINNER / 128, MROWS / 128), 256, SMEM_GEMM_BYTES>>>(
        pout, dt_proj_w, dt_proj_b, dt, MROWS, DINNER, DTRANK, 128, DTRANK, DINNER);

    // 6. selective scan + D*x + silu(z) gating
    scan_kernel<<<B_SZ * (DINNER / 16), 256>>>(xc, dt, pout, xz, A_log, Dp, ys);

    // 7. out = ys @ out_proj_w^T : (4096,2048) x (1024,2048)^T
    mma_gemm<0><<<dim3(DMODEL / 128, MROWS / 128), 256, SMEM_GEMM_BYTES>>>(
        ys, out_proj_w, nullptr, out, MROWS, DMODEL, DINNER, DINNER, DINNER, DMODEL);
}